// round 13
// baseline (speedup 1.0000x reference)
#include <cuda_runtime.h>
#include <cuda_bf16.h>
#include <cuda_fp16.h>
#include <cstdint>

#define N_SRC0 120000
#define N_DST0 40000
#define N_DST1 10000
#define T_REL  5
#define HID    128
#define IN_DIM 256
#define OUT_DIM 153
#define E0 800000
#define E1 300000
#define NEG_SLOPE 0.2f
#define EPS_LN 1e-5f

typedef __nv_bfloat16 bf16;

// ---------------- static device scratch ----------------
__device__ __align__(128) __half g_Hs0[(size_t)T_REL * N_SRC0 * HID];
__device__ __align__(128) __half g_Hs1[(size_t)T_REL * N_DST0 * HID];
__device__ __align__(16)  float g_el0[(size_t)T_REL * N_SRC0 * 4];
__device__ __align__(16)  float g_er0[(size_t)T_REL * N_DST0 * 4];
__device__ __align__(16)  float g_el1[(size_t)T_REL * N_DST0 * 4];
__device__ __align__(16)  float g_er1[(size_t)T_REL * N_DST1 * 4];
__device__ __align__(128) float g_acc0[(size_t)N_DST0 * HID];
__device__ __align__(128) float g_acc1[(size_t)N_DST1 * HID];
__device__ __align__(128) float g_mlp[(size_t)N_DST1 * HID];
__device__ int      g_cnt[T_REL * N_DST0];
__device__ int      g_offs[T_REL * (N_DST0 + 1)];
__device__ int      g_cur[T_REL * N_DST0];
__device__ int      g_eperm[T_REL * E0];      // stores SRC node id
__device__ double   g_colsum[HID];
__device__ double   g_colsq[HID];
__device__ float    g_mean[HID];
__device__ float    g_rstd[HID];
__device__ __align__(128) bf16 g_xhi[(size_t)N_SRC0 * IN_DIM];
__device__ __align__(128) bf16 g_xlo[(size_t)N_SRC0 * IN_DIM];
__device__ __align__(128) bf16 g_shi[(size_t)N_DST0 * HID];
__device__ __align__(128) bf16 g_slo[(size_t)N_DST0 * HID];
__device__ __align__(128) bf16 g_thi[(size_t)N_DST1 * HID];
__device__ __align__(128) bf16 g_tlo[(size_t)N_DST1 * HID];
#define W0T_OFF   0
#define WS0T_OFF  163840
#define W1T_OFF   196608
#define WS1T_OFF  278528
#define WM1T_OFF  294912
#define WM2T_OFF  311296
#define WT_TOTAL  330880
__device__ __align__(128) bf16 g_wthi[WT_TOTAL];
__device__ __align__(128) bf16 g_wtlo[WT_TOTAL];

// ---------------- helpers ----------------
__device__ __forceinline__ void cp_async16(uint32_t dst, const void* src, int sz) {
    asm volatile("cp.async.cg.shared.global [%0], [%1], 16, %2;\n"
                 :: "r"(dst), "l"(src), "r"(sz));
}
__device__ __forceinline__ void cp_commit() {
    asm volatile("cp.async.commit_group;\n");
}
__device__ __forceinline__ void ldsm4(uint32_t* r, uint32_t addr) {
    asm volatile("ldmatrix.sync.aligned.m8n8.x4.shared.b16 {%0,%1,%2,%3}, [%4];"
        : "=r"(r[0]), "=r"(r[1]), "=r"(r[2]), "=r"(r[3]) : "r"(addr));
}
__device__ __forceinline__ void mma16816(float* c, const uint32_t* a, uint32_t b0, uint32_t b1) {
    asm volatile("mma.sync.aligned.m16n8k16.row.col.f32.bf16.bf16.f32 "
        "{%0,%1,%2,%3}, {%4,%5,%6,%7}, {%8,%9}, {%0,%1,%2,%3};"
        : "+f"(c[0]), "+f"(c[1]), "+f"(c[2]), "+f"(c[3])
        : "r"(a[0]), "r"(a[1]), "r"(a[2]), "r"(a[3]), "r"(b0), "r"(b1));
}

// ---------------- split kernels ----------------
__global__ void split_kernel(const float* __restrict__ X, bf16* __restrict__ hi,
                             bf16* __restrict__ lo, size_t n)
{
    size_t i = (size_t)blockIdx.x * blockDim.x + threadIdx.x;
    if (i >= n) return;
    float v = X[i];
    bf16 h = __float2bfloat16(v);
    hi[i] = h;
    lo[i] = __float2bfloat16(v - __bfloat162float(h));
}
__global__ void splitw_all_kernel(
    const float* __restrict__ W0, const float* __restrict__ Ws0,
    const float* __restrict__ W1, const float* __restrict__ Ws1,
    const float* __restrict__ Wm1, const float* __restrict__ Wm2,
    bf16* __restrict__ hiT, bf16* __restrict__ loT)
{
    int seg = blockIdx.y;
    const float* W; int K, N, nrel, off;
    switch (seg) {
        case 0:  W = W0;  K = IN_DIM; N = HID;     nrel = T_REL; off = W0T_OFF;  break;
        case 1:  W = Ws0; K = IN_DIM; N = HID;     nrel = 1;     off = WS0T_OFF; break;
        case 2:  W = W1;  K = HID;    N = HID;     nrel = T_REL; off = W1T_OFF;  break;
        case 3:  W = Ws1; K = HID;    N = HID;     nrel = 1;     off = WS1T_OFF; break;
        case 4:  W = Wm1; K = HID;    N = HID;     nrel = 1;     off = WM1T_OFF; break;
        default: W = Wm2; K = HID;    N = OUT_DIM; nrel = 1;     off = WM2T_OFF; break;
    }
    int total = nrel * N * K;
    int idx = blockIdx.x * blockDim.x + threadIdx.x;
    if (idx >= total) return;
    int j = idx / (N * K);
    int rem = idx - j * (N * K);
    int n = rem / K, k = rem - n * K;
    float v = W[((size_t)j * K + k) * N + n];
    bf16 h = __float2bfloat16(v);
    hiT[off + idx] = h;
    loT[off + idx] = __float2bfloat16(v - __bfloat162float(h));
}

// ---------------- fused bf16x3 MMA GEMM, 3-stage pipeline, 512 threads --------
// 128x128 CTA tile, 16 warps in 4x4 grid, 32x32 warp tile; one sync per chunk.
#define GSTRIDE  40
#define SM_TILE  (128 * GSTRIDE)
#define SM_AHI   0
#define SM_ALO   SM_TILE
#define SM_BHI   (2 * SM_TILE)
#define SM_BLO   (3 * SM_TILE)
#define SM_STAGE (4 * SM_TILE)               // 20480 elements = 40960 B
#define SMEM_BYTES (3 * SM_STAGE * 2)        // 122880 B

template<bool REL, bool HASBIAS, bool EPI>
__global__ void __launch_bounds__(512, 1) mma_gemm3(
    const bf16* __restrict__ Ahi, const bf16* __restrict__ Alo,
    const bf16* __restrict__ BThi, const bf16* __restrict__ BTlo,
    const float* __restrict__ bias, void* __restrict__ Cv,
    const float* __restrict__ al, const float* __restrict__ ar,
    float* __restrict__ el, float* __restrict__ er,
    int M, int N, int K, int n_er)
{
    extern __shared__ bf16 sm[];

    __half* Ch = (__half*)Cv;
    float*  Cf = (float*)Cv;

    int bm0, bn0, ldc;
    if (REL) {
        int j = blockIdx.x;
        bm0 = blockIdx.y * 128;
        BThi += (size_t)j * 128 * K;
        BTlo += (size_t)j * 128 * K;
        Ch   += (size_t)j * M * 128;
        if (EPI) {
            al += (size_t)j * HID;  ar += (size_t)j * HID;
            el += (size_t)j * M * 4; er += (size_t)j * n_er * 4;
        }
        bn0 = 0; ldc = 128; N = 128;
    } else {
        bm0 = blockIdx.x * 128;
        bn0 = blockIdx.y * 128; ldc = N;
    }

    int tid = threadIdx.x, lane = tid & 31, warp = tid >> 5;   // warp 0..15
    int wm = (warp & 3) * 32, wn = (warp >> 2) * 32;

    int kc = K >> 5;

    int ldrow = tid >> 2;            // 0..127
    int ldcol = (tid & 3) << 3;      // 0,8,16,24 elements

    uint32_t s0 = (uint32_t)__cvta_generic_to_shared(sm);

    int mrowA = lane & 15, mcolA = (lane >> 4) << 3;
    int mrowB = (lane & 7) | ((lane >> 4) << 3);
    int mcolB = ((lane >> 3) & 1) << 3;

    float acc[2][4][4];               // [mt][n8-tile][4]
#pragma unroll
    for (int a = 0; a < 2; a++)
#pragma unroll
        for (int b = 0; b < 4; b++)
#pragma unroll
            for (int c = 0; c < 4; c++) acc[a][b][c] = 0.f;

#define LOAD_STAGE(IT, ST) do {                                                  \
    int kk_ = (IT) << 5;                                                         \
    uint32_t sb_ = s0 + (uint32_t)(ST) * (SM_STAGE * 2);                         \
    int gm_ = bm0 + ldrow;                                                       \
    int oka_ = gm_ < M;                                                          \
    size_t aoff_ = (size_t)(oka_ ? gm_ : 0) * K + kk_ + ldcol;                   \
    cp_async16(sb_ + (SM_AHI + ldrow * GSTRIDE + ldcol) * 2, Ahi + aoff_, oka_ ? 16 : 0); \
    cp_async16(sb_ + (SM_ALO + ldrow * GSTRIDE + ldcol) * 2, Alo + aoff_, oka_ ? 16 : 0); \
    int gn_ = bn0 + ldrow;                                                       \
    int okb_ = gn_ < N;                                                          \
    size_t boff_ = (size_t)(okb_ ? gn_ : 0) * K + kk_ + ldcol;                   \
    cp_async16(sb_ + (SM_BHI + ldrow * GSTRIDE + ldcol) * 2, BThi + boff_, okb_ ? 16 : 0); \
    cp_async16(sb_ + (SM_BLO + ldrow * GSTRIDE + ldcol) * 2, BTlo + boff_, okb_ ? 16 : 0); \
    cp_commit();                                                                 \
} while (0)

    LOAD_STAGE(0, 0);
    LOAD_STAGE(1, 1);

    for (int it = 0; it < kc; it++) {
        int st = it % 3;
        if (it + 1 < kc) {
            asm volatile("cp.async.wait_group 1;\n" ::: "memory");
        } else {
            asm volatile("cp.async.wait_group 0;\n" ::: "memory");
        }
        __syncthreads();

        uint32_t base = s0 + (uint32_t)st * (SM_STAGE * 2);
#pragma unroll
        for (int s = 0; s < 2; s++) {
            uint32_t ahi[2][4], alo2[2][4];
#pragma unroll
            for (int mt = 0; mt < 2; mt++) {
                uint32_t ra = (wm + mt * 16 + mrowA) * GSTRIDE + s * 16 + mcolA;
                ldsm4(ahi[mt],  base + (SM_AHI + ra) * 2);
                ldsm4(alo2[mt], base + (SM_ALO + ra) * 2);
            }
#pragma unroll
            for (int nb = 0; nb < 2; nb++) {
                uint32_t bh[4];
                ldsm4(bh, base + (SM_BHI + (wn + nb * 16 + mrowB) * GSTRIDE + s * 16 + mcolB) * 2);
#pragma unroll
                for (int mt = 0; mt < 2; mt++) {
                    mma16816(acc[mt][2 * nb],     ahi[mt],  bh[0], bh[1]);
                    mma16816(acc[mt][2 * nb + 1], ahi[mt],  bh[2], bh[3]);
                    mma16816(acc[mt][2 * nb],     alo2[mt], bh[0], bh[1]);
                    mma16816(acc[mt][2 * nb + 1], alo2[mt], bh[2], bh[3]);
                }
            }
#pragma unroll
            for (int nb = 0; nb < 2; nb++) {
                uint32_t bl[4];
                ldsm4(bl, base + (SM_BLO + (wn + nb * 16 + mrowB) * GSTRIDE + s * 16 + mcolB) * 2);
#pragma unroll
                for (int mt = 0; mt < 2; mt++) {
                    mma16816(acc[mt][2 * nb],     ahi[mt], bl[0], bl[1]);
                    mma16816(acc[mt][2 * nb + 1], ahi[mt], bl[2], bl[3]);
                }
            }
        }
        if (it + 2 < kc) LOAD_STAGE(it + 2, (it + 2) % 3);
    }
#undef LOAD_STAGE

    int trow = lane >> 2, tcol = (lane & 3) << 1;
#pragma unroll
    for (int mt = 0; mt < 2; mt++) {
        int gm0 = bm0 + wm + mt * 16 + trow;
        int gm1 = gm0 + 8;
#pragma unroll
        for (int nn = 0; nn < 4; nn++) {
            int gn = bn0 + wn + nn * 8 + tcol;
            float* cr = acc[mt][nn];
            if (REL) {
                if (gm0 < M) {
                    Ch[(size_t)gm0 * ldc + gn]     = __float2half(cr[0]);
                    Ch[(size_t)gm0 * ldc + gn + 1] = __float2half(cr[1]);
                }
                if (gm1 < M) {
                    Ch[(size_t)gm1 * ldc + gn]     = __float2half(cr[2]);
                    Ch[(size_t)gm1 * ldc + gn + 1] = __float2half(cr[3]);
                }
            } else {
                bool okn0 = gn < N, okn1 = gn + 1 < N;
                float b0a = 0.f, b1a = 0.f;
                if (HASBIAS) {
                    if (okn0) b0a = bias[gn];
                    if (okn1) b1a = bias[gn + 1];
                }
                if (gm0 < M) {
                    if (okn0) Cf[(size_t)gm0 * ldc + gn]     = cr[0] + b0a;
                    if (okn1) Cf[(size_t)gm0 * ldc + gn + 1] = cr[1] + b1a;
                }
                if (gm1 < M) {
                    if (okn0) Cf[(size_t)gm1 * ldc + gn]     = cr[2] + b0a;
                    if (okn1) Cf[(size_t)gm1 * ldc + gn + 1] = cr[3] + b1a;
                }
            }
        }
        if (EPI) {
            // each warp owns exactly one head: cols [wn, wn+32)
            int head = warp >> 2;
            float e0 = 0.f, e1 = 0.f, r0 = 0.f, r1 = 0.f;
#pragma unroll
            for (int nn = 0; nn < 4; nn++) {
                int gn = wn + nn * 8 + tcol;
                float a0v = al[gn], a1v = al[gn + 1];
                float r0v = ar[gn], r1v = ar[gn + 1];
                float* cr = acc[mt][nn];
                e0 += cr[0] * a0v + cr[1] * a1v;
                e1 += cr[2] * a0v + cr[3] * a1v;
                r0 += cr[0] * r0v + cr[1] * r1v;
                r1 += cr[2] * r0v + cr[3] * r1v;
            }
#pragma unroll
            for (int d = 1; d < 4; d <<= 1) {
                e0 += __shfl_xor_sync(0xffffffffu, e0, d);
                e1 += __shfl_xor_sync(0xffffffffu, e1, d);
                r0 += __shfl_xor_sync(0xffffffffu, r0, d);
                r1 += __shfl_xor_sync(0xffffffffu, r1, d);
            }
            if ((lane & 3) == 0) {
                if (gm0 < M) {
                    el[(size_t)gm0 * 4 + head] = e0;
                    if (gm0 < n_er) er[(size_t)gm0 * 4 + head] = r0;
                }
                if (gm1 < M) {
                    el[(size_t)gm1 * 4 + head] = e1;
                    if (gm1 < n_er) er[(size_t)gm1 * 4 + head] = r1;
                }
            }
        }
    }
}

// ---------------- CSR build ----------------
__global__ void fill_int_kernel(int* p, int n, int v) {
    int i = blockIdx.x * blockDim.x + threadIdx.x;
    if (i < n) p[i] = v;
}
__global__ void hist_kernel(const int* __restrict__ dstAll, int E, int* __restrict__ cnt) {
    int j = blockIdx.y;
    int e = blockIdx.x * blockDim.x + threadIdx.x;
    if (e < E) atomicAdd(&cnt[j * N_DST0 + dstAll[(size_t)j * E + e]], 1);
}
__global__ void scan_kernel(const int* __restrict__ cntAll, int* __restrict__ offsAll,
                            int* __restrict__ curAll, int n) {
    const int* cnt = cntAll + blockIdx.x * N_DST0;
    int* offs = offsAll + blockIdx.x * (N_DST0 + 1);
    int* cur  = curAll + blockIdx.x * N_DST0;
    __shared__ int wsum[32];
    __shared__ int running_s;
    if (threadIdx.x == 0) running_s = 0;
    __syncthreads();
    int lane = threadIdx.x & 31, wid = threadIdx.x >> 5;
    for (int base = 0; base < n; base += 1024) {
        int i = base + (int)threadIdx.x;
        int v = (i < n) ? cnt[i] : 0;
        int x = v;
#pragma unroll
        for (int d = 1; d < 32; d <<= 1) {
            int t = __shfl_up_sync(0xffffffffu, x, d);
            if (lane >= d) x += t;
        }
        if (lane == 31) wsum[wid] = x;
        __syncthreads();
        if (wid == 0) {
            int y = wsum[lane];
#pragma unroll
            for (int d = 1; d < 32; d <<= 1) {
                int t = __shfl_up_sync(0xffffffffu, y, d);
                if (lane >= d) y += t;
            }
            wsum[lane] = y;
        }
        __syncthreads();
        int incl = x + (wid ? wsum[wid - 1] : 0);
        int r = running_s;
        if (i < n) { int o = r + (incl - v); offs[i] = o; cur[i] = o; }
        int total = wsum[31];
        __syncthreads();
        if (threadIdx.x == 0) running_s = r + total;
        __syncthreads();
    }
    if (threadIdx.x == 0) offs[n] = running_s;
}
__global__ void scatter_kernel(const int* __restrict__ srcAll,
                               const int* __restrict__ dstAll, int E,
                               int* __restrict__ cur, int* __restrict__ eperm)
{
    int j = blockIdx.y;
    int e = blockIdx.x * blockDim.x + threadIdx.x;
    if (e >= E) return;
    int s = srcAll[(size_t)j * E + e];
    int d = dstAll[(size_t)j * E + e];
    int pos = atomicAdd(&cur[j * N_DST0 + d], 1);
    eperm[(size_t)j * E0 + pos] = s;
}

// ---------------- aggregation: one block (64 thr) per (dst, relation) ----------
__global__ void aggregate_rel_kernel(
    const __half* __restrict__ Hs, int hsrows,
    const float* __restrict__ el, const float* __restrict__ er,
    const int* __restrict__ offs, const int* __restrict__ eperm,
    int n_dst, float* __restrict__ out)
{
    int nd = blockIdx.x;
    int j = blockIdx.y;
    int t = threadIdx.x;              // 0..63, columns 2t, 2t+1
    int h = t >> 4;                   // head of cols 2t,2t+1

    const __half* Hj = Hs + (size_t)j * hsrows * HID;
    const float* elj = el + (size_t)j * hsrows * 4;
    const float* erj = er + (size_t)j * n_dst * 4;
    const int* offj = offs + j * (N_DST0 + 1);
    const int* epj  = eperm + (size_t)j * E0;

    int o0 = offj[nd], o1 = offj[nd + 1];
    int cnt = o1 - o0;
    if (cnt == 0) return;

    __shared__ int   s_src[64];
    __shared__ float s_w[4][64];

    float er_all[4];
    {
        float4 e4 = *(const float4*)(erj + (size_t)nd * 4);
        er_all[0] = e4.x; er_all[1] = e4.y; er_all[2] = e4.z; er_all[3] = e4.w;
    }
    float2 acc = make_float2(0.f, 0.f);
    float ssum = 0.f;
    for (int c0 = 0; c0 < cnt; c0 += 64) {
        int k = c0 + t;
        if (k < cnt) {
            int s = epj[o0 + k];
            s_src[t] = s;
            float4 L = *(const float4*)(elj + (size_t)s * 4);
            float lv[4] = {L.x, L.y, L.z, L.w};
#pragma unroll
            for (int hh = 0; hh < 4; hh++) {
                float v = lv[hh] + er_all[hh];
                v = v > 0.f ? v : NEG_SLOPE * v;
                s_w[hh][t] = __expf(v);
            }
        }
        __syncthreads();
        int len = min(64, cnt - c0);
        const float* wrow = s_w[h];
#pragma unroll 4
        for (int k2 = 0; k2 < len; k2++) {
            float w = wrow[k2];
            __half2 x2 = *(const __half2*)(Hj + (size_t)s_src[k2] * HID + 2 * t);
            float2 xf = __half22float2(x2);
            acc.x += w * xf.x;
            acc.y += w * xf.y;
            ssum += w;
        }
        __syncthreads();
    }
    float inv = 1.f / ssum;
    float* op = out + (size_t)nd * HID + 2 * t;
    atomicAdd(op,     acc.x * inv);
    atomicAdd(op + 1, acc.y * inv);
}

// ---------------- column norm + activation ----------------
__global__ void colstat_zero_kernel() {
    int t = threadIdx.x;
    g_colsum[t] = 0.0; g_colsq[t] = 0.0;
}
__global__ void colstat_partial_kernel(const float* __restrict__ X, int nrows) {
    int t = threadIdx.x;
    int r0 = blockIdx.x * 256;
    int r1 = min(r0 + 256, nrows);
    float fs = 0.f, fq = 0.f;
    for (int r = r0; r < r1; r++) {
        float v = X[(size_t)r * HID + t];
        fs += v; fq += v * v;
    }
    atomicAdd(&g_colsum[t], (double)fs);
    atomicAdd(&g_colsq[t], (double)fq);
}
__global__ void colstat_final_kernel(int nrows) {
    int t = threadIdx.x;
    double inv = 1.0 / (double)nrows;
    double mean = g_colsum[t] * inv;
    double var = g_colsq[t] * inv - mean * mean;
    g_mean[t] = (float)mean;
    g_rstd[t] = (float)(1.0 / sqrt(var + (double)EPS_LN));
}
__global__ void norm_act_split_kernel(const float* __restrict__ X,
                                      const float* __restrict__ g,
                                      const float* __restrict__ be,
                                      bf16* __restrict__ hi, bf16* __restrict__ lo,
                                      int nrows, int act)
{
    int idx = blockIdx.x * blockDim.x + threadIdx.x;
    if (idx >= nrows * HID) return;
    int t = idx & (HID - 1);
    float v = (X[idx] - g_mean[t]) * g_rstd[t] * g[t] + be[t];
    if (act) v = v > 0.f ? v : 0.f;
    else     v = v > 0.f ? v : expm1f(v);
    bf16 h = __float2bfloat16(v);
    hi[idx] = h;
    lo[idx] = __float2bfloat16(v - __bfloat162float(h));
}

// ---------------- host orchestration ----------------
static inline void* sym(const void* s) { void* p = nullptr; cudaGetSymbolAddress(&p, s); return p; }

static void set_smem_attrs() {
    cudaFuncSetAttribute(mma_gemm3<true,  false, true >, cudaFuncAttributeMaxDynamicSharedMemorySize, SMEM_BYTES);
    cudaFuncSetAttribute(mma_gemm3<false, true,  false>, cudaFuncAttributeMaxDynamicSharedMemorySize, SMEM_BYTES);
}

static void run_layer(const bf16* Ahi, const bf16* Alo, int n_src, int n_dst, int Kdim,
                      const bf16* WtHi, const bf16* WtLo,
                      const bf16* WsHi, const bf16* WsLo,
                      const float* alpha_l, const float* alpha_r,
                      const float* bs,
                      const float* gamma, const float* beta,
                      const int* srcAll, const int* dstAll, int E,
                      __half* Hs, float* elbuf, float* erbuf,
                      float* accbuf, bf16* outhi, bf16* outlo)
{
    int* cnt = (int*)sym(g_cnt);
    int* offs = (int*)sym(g_offs);
    int* cur = (int*)sym(g_cur);
    int* eperm = (int*)sym(g_eperm);

    fill_int_kernel<<<(T_REL * N_DST0 + 255) / 256, 256>>>(cnt, T_REL * N_DST0, 0);

    {   // Hs = A @ W[j]^T for all relations (grid.x = relation for A-tile L2 reuse)
        dim3 grid(T_REL, (n_src + 127) / 128);
        mma_gemm3<true, false, true><<<grid, 512, SMEM_BYTES>>>(
            Ahi, Alo, WtHi, WtLo, nullptr, Hs,
            alpha_l, alpha_r, elbuf, erbuf, n_src, HID, Kdim, n_dst);
    }

    { dim3 grid((E + 255) / 256, T_REL);
      hist_kernel<<<grid, 256>>>(dstAll, E, cnt); }
    scan_kernel<<<T_REL, 1024>>>(cnt, offs, cur, n_dst);
    { dim3 grid((E + 255) / 256, T_REL);
      scatter_kernel<<<grid, 256>>>(srcAll, dstAll, E, cur, eperm); }

    {   // acc = A[:n_dst] @ Ws + bs (fp32 out)
        dim3 grid((n_dst + 127) / 128, 1);
        mma_gemm3<false, true, false><<<grid, 512, SMEM_BYTES>>>(
            Ahi, Alo, WsHi, WsLo, bs, accbuf,
            nullptr, nullptr, nullptr, nullptr, n_dst, HID, Kdim, 0);
    }

    { dim3 grid(n_dst, T_REL);
      aggregate_rel_kernel<<<grid, 64>>>(Hs, n_src, elbuf, erbuf, offs, eperm,
                                         n_dst, accbuf); }

    colstat_zero_kernel<<<1, 128>>>();
    colstat_partial_kernel<<<(n_dst + 255) / 256, 128>>>(accbuf, n_dst);
    colstat_final_kernel<<<1, 128>>>(n_dst);
    norm_act_split_kernel<<<(n_dst * HID + 255) / 256, 256>>>(accbuf, gamma, beta,
                                                              outhi, outlo, n_dst, 0);
}

extern "C" void kernel_launch(void* const* d_in, const int* in_sizes, int n_in,
                              void* d_out, int out_size)
{
    (void)in_sizes; (void)n_in; (void)out_size;
    const float* x   = (const float*)d_in[0];
    const float* W0  = (const float*)d_in[1];
    const float* al0 = (const float*)d_in[2];
    const float* ar0 = (const float*)d_in[3];
    const float* Ws0 = (const float*)d_in[5];
    const float* bs0 = (const float*)d_in[6];
    const float* g0  = (const float*)d_in[7];
    const float* be0 = (const float*)d_in[8];
    const float* W1  = (const float*)d_in[9];
    const float* al1 = (const float*)d_in[10];
    const float* ar1 = (const float*)d_in[11];
    const float* Ws1 = (const float*)d_in[13];
    const float* bs1 = (const float*)d_in[14];
    const float* g1  = (const float*)d_in[15];
    const float* be1 = (const float*)d_in[16];
    const float* Wm1 = (const float*)d_in[17];
    const float* bm1 = (const float*)d_in[18];
    const float* gm  = (const float*)d_in[19];
    const float* bem = (const float*)d_in[20];
    const float* Wm2 = (const float*)d_in[21];
    const float* bm2 = (const float*)d_in[22];
    const int* src0  = (const int*)d_in[23];
    const int* dst0  = (const int*)d_in[24];
    const int* src1  = (const int*)d_in[25];
    const int* dst1  = (const int*)d_in[26];
    float* out = (float*)d_out;

    __half* Hs0 = (__half*)sym(g_Hs0);
    __half* Hs1 = (__half*)sym(g_Hs1);
    float* el0p = (float*)sym(g_el0);
    float* er0p = (float*)sym(g_er0);
    float* el1p = (float*)sym(g_el1);
    float* er1p = (float*)sym(g_er1);
    float* acc0 = (float*)sym(g_acc0);
    float* acc1 = (float*)sym(g_acc1);
    float* mlp  = (float*)sym(g_mlp);
    bf16* xhi = (bf16*)sym(g_xhi);
    bf16* xlo = (bf16*)sym(g_xlo);
    bf16* shi = (bf16*)sym(g_shi);
    bf16* slo = (bf16*)sym(g_slo);
    bf16* thi = (bf16*)sym(g_thi);
    bf16* tlo = (bf16*)sym(g_tlo);
    bf16* wthi = (bf16*)sym(g_wthi);
    bf16* wtlo = (bf16*)sym(g_wtlo);

    set_smem_attrs();

    {
        dim3 g((T_REL * HID * IN_DIM + 255) / 256, 6);
        splitw_all_kernel<<<g, 256>>>(W0, Ws0, W1, Ws1, Wm1, Wm2, wthi, wtlo);
    }
    {
        size_t n = (size_t)N_SRC0 * IN_DIM;
        split_kernel<<<(unsigned)((n + 255) / 256), 256>>>(x, xhi, xlo, n);
    }

    // Layer 0
    run_layer(xhi, xlo, N_SRC0, N_DST0, IN_DIM,
              wthi + W0T_OFF, wtlo + W0T_OFF, wthi + WS0T_OFF, wtlo + WS0T_OFF,
              al0, ar0, bs0, g0, be0,
              src0, dst0, E0, Hs0, el0p, er0p, acc0, shi, slo);

    // Layer 1
    run_layer(shi, slo, N_DST0, N_DST1, HID,
              wthi + W1T_OFF, wtlo + W1T_OFF, wthi + WS1T_OFF, wtlo + WS1T_OFF,
              al1, ar1, bs1, g1, be1,
              src1, dst1, E1, Hs1, el1p, er1p, acc1, thi, tlo);

    // MLP
    {
        dim3 grid((N_DST1 + 127) / 128, 1);
        mma_gemm3<false, true, false><<<grid, 512, SMEM_BYTES>>>(
            thi, tlo, wthi + WM1T_OFF, wtlo + WM1T_OFF, bm1, mlp,
            nullptr, nullptr, nullptr, nullptr, N_DST1, HID, HID, 0);
    }
    colstat_zero_kernel<<<1, 128>>>();
    colstat_partial_kernel<<<(N_DST1 + 255) / 256, 128>>>(mlp, N_DST1);
    colstat_final_kernel<<<1, 128>>>(N_DST1);
    norm_act_split_kernel<<<(N_DST1 * HID + 255) / 256, 256>>>(mlp, gm, bem, shi, slo, N_DST1, 1);
    {
        dim3 grid((N_DST1 + 127) / 128, (OUT_DIM + 127) / 128);
        mma_gemm3<false, true, false><<<grid, 512, SMEM_BYTES>>>(
            shi, slo, wthi + WM2T_OFF, wtlo + WM2T_OFF, bm2, out,
            nullptr, nullptr, nullptr, nullptr, N_DST1, OUT_DIM, HID, 0);
    }
}

// round 16
// speedup vs baseline: 1.1637x; 1.1637x over previous
#include <cuda_runtime.h>
#include <cuda_fp16.h>
#include <cstdint>

#define N_SRC0 120000
#define N_DST0 40000
#define N_DST1 10000
#define T_REL  5
#define HID    128
#define IN_DIM 256
#define OUT_DIM 153
#define E0 800000
#define E1 300000
#define NEG_SLOPE 0.2f
#define EPS_LN 1e-5f

typedef __half fp16;

// ---------------- static device scratch ----------------
__device__ __align__(128) __half g_Hs0[(size_t)T_REL * N_SRC0 * HID];
__device__ __align__(128) __half g_Hs1[(size_t)T_REL * N_DST0 * HID];
__device__ __align__(16)  float g_el0[(size_t)T_REL * N_SRC0 * 4];
__device__ __align__(16)  float g_er0[(size_t)T_REL * N_DST0 * 4];
__device__ __align__(16)  float g_el1[(size_t)T_REL * N_DST0 * 4];
__device__ __align__(16)  float g_er1[(size_t)T_REL * N_DST1 * 4];
__device__ __align__(128) float g_acc0[(size_t)N_DST0 * HID];
__device__ __align__(128) float g_acc1[(size_t)N_DST1 * HID];
__device__ __align__(128) float g_mlp[(size_t)N_DST1 * HID];
__device__ int      g_cnt[T_REL * N_DST0];
__device__ int      g_offs[T_REL * (N_DST0 + 1)];
__device__ int      g_cur[T_REL * N_DST0];
__device__ int      g_eperm[T_REL * E0];      // stores SRC node id
__device__ double   g_colsum[HID];
__device__ double   g_colsq[HID];
__device__ float    g_mean[HID];
__device__ float    g_rstd[HID];
__device__ __align__(128) fp16 g_xhi[(size_t)N_SRC0 * IN_DIM];
__device__ __align__(128) fp16 g_xlo[(size_t)N_SRC0 * IN_DIM];
__device__ __align__(128) fp16 g_shi[(size_t)N_DST0 * HID];
__device__ __align__(128) fp16 g_slo[(size_t)N_DST0 * HID];
__device__ __align__(128) fp16 g_thi[(size_t)N_DST1 * HID];
__device__ __align__(128) fp16 g_tlo[(size_t)N_DST1 * HID];
#define W0T_OFF   0
#define WS0T_OFF  163840
#define W1T_OFF   196608
#define WS1T_OFF  278528
#define WM1T_OFF  294912
#define WM2T_OFF  311296
#define WT_TOTAL  330880
__device__ __align__(128) fp16 g_wt[WT_TOTAL];   // single fp16 weights [N][K]

// ---------------- helpers ----------------
__device__ __forceinline__ void cp_async16(uint32_t dst, const void* src, int sz) {
    asm volatile("cp.async.cg.shared.global [%0], [%1], 16, %2;\n"
                 :: "r"(dst), "l"(src), "r"(sz));
}
__device__ __forceinline__ void cp_commit() {
    asm volatile("cp.async.commit_group;\n");
}
__device__ __forceinline__ void ldsm4(uint32_t* r, uint32_t addr) {
    asm volatile("ldmatrix.sync.aligned.m8n8.x4.shared.b16 {%0,%1,%2,%3}, [%4];"
        : "=r"(r[0]), "=r"(r[1]), "=r"(r[2]), "=r"(r[3]) : "r"(addr));
}
__device__ __forceinline__ void mma16816(float* c, const uint32_t* a, uint32_t b0, uint32_t b1) {
    asm volatile("mma.sync.aligned.m16n8k16.row.col.f32.f16.f16.f32 "
        "{%0,%1,%2,%3}, {%4,%5,%6,%7}, {%8,%9}, {%0,%1,%2,%3};"
        : "+f"(c[0]), "+f"(c[1]), "+f"(c[2]), "+f"(c[3])
        : "r"(a[0]), "r"(a[1]), "r"(a[2]), "r"(a[3]), "r"(b0), "r"(b1));
}

// ---------------- split kernels ----------------
__global__ void split_kernel(const float* __restrict__ X, fp16* __restrict__ hi,
                             fp16* __restrict__ lo, size_t n)
{
    size_t i = (size_t)blockIdx.x * blockDim.x + threadIdx.x;
    if (i >= n) return;
    float v = X[i];
    fp16 h = __float2half(v);
    hi[i] = h;
    lo[i] = __float2half(v - __half2float(h));
}
// transpose + fp16 round (weights single-precision-fp16)
__global__ void splitw_all_kernel(
    const float* __restrict__ W0, const float* __restrict__ Ws0,
    const float* __restrict__ W1, const float* __restrict__ Ws1,
    const float* __restrict__ Wm1, const float* __restrict__ Wm2,
    fp16* __restrict__ wT)
{
    int seg = blockIdx.y;
    const float* W; int K, N, nrel, off;
    switch (seg) {
        case 0:  W = W0;  K = IN_DIM; N = HID;     nrel = T_REL; off = W0T_OFF;  break;
        case 1:  W = Ws0; K = IN_DIM; N = HID;     nrel = 1;     off = WS0T_OFF; break;
        case 2:  W = W1;  K = HID;    N = HID;     nrel = T_REL; off = W1T_OFF;  break;
        case 3:  W = Ws1; K = HID;    N = HID;     nrel = 1;     off = WS1T_OFF; break;
        case 4:  W = Wm1; K = HID;    N = HID;     nrel = 1;     off = WM1T_OFF; break;
        default: W = Wm2; K = HID;    N = OUT_DIM; nrel = 1;     off = WM2T_OFF; break;
    }
    int total = nrel * N * K;
    int idx = blockIdx.x * blockDim.x + threadIdx.x;
    if (idx >= total) return;
    int j = idx / (N * K);
    int rem = idx - j * (N * K);
    int n = rem / K, k = rem - n * K;
    wT[off + idx] = __float2half(W[((size_t)j * K + k) * N + n]);
}

// ---------------- fused fp16x2 MMA GEMM, 3-stage, 256 thr, 2 CTA/SM ----------
// A split hi/lo (fp16) [M][K]; W fp16 [N][K]. acc += Ahi*B + Alo*B (= A_fp32*B_fp16).
#define GSTRIDE  40
#define SM_TILE  (128 * GSTRIDE)
#define SM_AHI   0
#define SM_ALO   SM_TILE
#define SM_B     (2 * SM_TILE)
#define SM_STAGE (3 * SM_TILE)               // 15360 elements = 30720 B
#define SMEM_BYTES (3 * SM_STAGE * 2)        // 92160 B

template<bool REL, bool HASBIAS, bool EPI>
__global__ void __launch_bounds__(256, 2) mma_gemm4(
    const fp16* __restrict__ Ahi, const fp16* __restrict__ Alo,
    const fp16* __restrict__ BT,
    const float* __restrict__ bias, void* __restrict__ Cv,
    const float* __restrict__ al, const float* __restrict__ ar,
    float* __restrict__ el, float* __restrict__ er,
    int M, int N, int K, int n_er)
{
    extern __shared__ fp16 sm[];

    __half* Ch = (__half*)Cv;
    float*  Cf = (float*)Cv;

    int bm0, bn0, ldc;
    if (REL) {
        int j = blockIdx.x;
        bm0 = blockIdx.y * 128;
        BT += (size_t)j * 128 * K;
        Ch += (size_t)j * M * 128;
        if (EPI) {
            al += (size_t)j * HID;  ar += (size_t)j * HID;
            el += (size_t)j * M * 4; er += (size_t)j * n_er * 4;
        }
        bn0 = 0; ldc = 128; N = 128;
    } else {
        bm0 = blockIdx.x * 128;
        bn0 = blockIdx.y * 128; ldc = N;
    }

    int tid = threadIdx.x, lane = tid & 31, warp = tid >> 5;
    int wm = (warp & 3) * 32, wn = (warp >> 2) * 64;

    int kc = K >> 5;

    int ldrow = tid >> 2;            // 0..63 (+64 via hh)
    int ldcol = (tid & 3) << 3;

    uint32_t s0 = (uint32_t)__cvta_generic_to_shared(sm);

    int mrowA = lane & 15, mcolA = (lane >> 4) << 3;
    int mrowB = (lane & 7) | ((lane >> 4) << 3);
    int mcolB = ((lane >> 3) & 1) << 3;

    float acc[2][8][4];
#pragma unroll
    for (int a = 0; a < 2; a++)
#pragma unroll
        for (int b = 0; b < 8; b++)
#pragma unroll
            for (int c = 0; c < 4; c++) acc[a][b][c] = 0.f;

#define LOAD_STAGE(IT, ST) do {                                                  \
    int kk_ = (IT) << 5;                                                         \
    uint32_t sb_ = s0 + (uint32_t)(ST) * (SM_STAGE * 2);                         \
    _Pragma("unroll")                                                            \
    for (int hh = 0; hh < 2; hh++) {                                             \
        int row = ldrow + hh * 64;                                               \
        int gm = bm0 + row;                                                      \
        int ok = gm < M;                                                         \
        size_t aoff = (size_t)(ok ? gm : 0) * K + kk_ + ldcol;                   \
        cp_async16(sb_ + (SM_AHI + row * GSTRIDE + ldcol) * 2, Ahi + aoff, ok ? 16 : 0); \
        cp_async16(sb_ + (SM_ALO + row * GSTRIDE + ldcol) * 2, Alo + aoff, ok ? 16 : 0); \
        int gn = bn0 + row;                                                      \
        int okb = gn < N;                                                        \
        size_t boff = (size_t)(okb ? gn : 0) * K + kk_ + ldcol;                  \
        cp_async16(sb_ + (SM_B + row * GSTRIDE + ldcol) * 2, BT + boff, okb ? 16 : 0); \
    }                                                                            \
    cp_commit();                                                                 \
} while (0)

    LOAD_STAGE(0, 0);
    LOAD_STAGE(1, 1);

    for (int it = 0; it < kc; it++) {
        int st = it % 3;
        if (it + 1 < kc) {
            asm volatile("cp.async.wait_group 1;\n" ::: "memory");
        } else {
            asm volatile("cp.async.wait_group 0;\n" ::: "memory");
        }
        __syncthreads();

        uint32_t base = s0 + (uint32_t)st * (SM_STAGE * 2);
#pragma unroll
        for (int s = 0; s < 2; s++) {
            uint32_t ahi[2][4], alo2[2][4];
#pragma unroll
            for (int mt = 0; mt < 2; mt++) {
                uint32_t ra = (wm + mt * 16 + mrowA) * GSTRIDE + s * 16 + mcolA;
                ldsm4(ahi[mt],  base + (SM_AHI + ra) * 2);
                ldsm4(alo2[mt], base + (SM_ALO + ra) * 2);
            }
#pragma unroll
            for (int np = 0; np < 4; np++) {
                uint32_t b[4];
                ldsm4(b, base + (SM_B + (wn + np * 16 + mrowB) * GSTRIDE + s * 16 + mcolB) * 2);
#pragma unroll
                for (int mt = 0; mt < 2; mt++) {
                    mma16816(acc[mt][2 * np],     ahi[mt],  b[0], b[1]);
                    mma16816(acc[mt][2 * np + 1], ahi[mt],  b[2], b[3]);
                    mma16816(acc[mt][2 * np],     alo2[mt], b[0], b[1]);
                    mma16816(acc[mt][2 * np + 1], alo2[mt], b[2], b[3]);
                }
            }
        }
        if (it + 2 < kc) LOAD_STAGE(it + 2, (it + 2) % 3);
    }
#undef LOAD_STAGE

    int trow = lane >> 2, tcol = (lane & 3) << 1;
#pragma unroll
    for (int mt = 0; mt < 2; mt++) {
        int gm0 = bm0 + wm + mt * 16 + trow;
        int gm1 = gm0 + 8;
#pragma unroll
        for (int nt = 0; nt < 8; nt++) {
            int gn = bn0 + wn + nt * 8 + tcol;
            float* cr = acc[mt][nt];
            if (REL) {
                if (gm0 < M) {
                    Ch[(size_t)gm0 * ldc + gn]     = __float2half(cr[0]);
                    Ch[(size_t)gm0 * ldc + gn + 1] = __float2half(cr[1]);
                }
                if (gm1 < M) {
                    Ch[(size_t)gm1 * ldc + gn]     = __float2half(cr[2]);
                    Ch[(size_t)gm1 * ldc + gn + 1] = __float2half(cr[3]);
                }
            } else {
                bool okn0 = gn < N, okn1 = gn + 1 < N;
                float b0a = 0.f, b1a = 0.f;
                if (HASBIAS) {
                    if (okn0) b0a = bias[gn];
                    if (okn1) b1a = bias[gn + 1];
                }
                if (gm0 < M) {
                    if (okn0) Cf[(size_t)gm0 * ldc + gn]     = cr[0] + b0a;
                    if (okn1) Cf[(size_t)gm0 * ldc + gn + 1] = cr[1] + b1a;
                }
                if (gm1 < M) {
                    if (okn0) Cf[(size_t)gm1 * ldc + gn]     = cr[2] + b0a;
                    if (okn1) Cf[(size_t)gm1 * ldc + gn + 1] = cr[3] + b1a;
                }
            }
        }
        if (EPI) {
            float eA0 = 0.f, eB0 = 0.f, rA0 = 0.f, rB0 = 0.f;
            float eA1 = 0.f, eB1 = 0.f, rA1 = 0.f, rB1 = 0.f;
#pragma unroll
            for (int nt = 0; nt < 8; nt++) {
                int gn = wn + nt * 8 + tcol;
                float a0v = al[gn], a1v = al[gn + 1];
                float r0v = ar[gn], r1v = ar[gn + 1];
                float* cr = acc[mt][nt];
                float c0 = cr[0] * a0v + cr[1] * a1v;
                float c1 = cr[2] * a0v + cr[3] * a1v;
                float d0 = cr[0] * r0v + cr[1] * r1v;
                float d1 = cr[2] * r0v + cr[3] * r1v;
                if (nt < 4) { eA0 += c0; eA1 += c1; rA0 += d0; rA1 += d1; }
                else        { eB0 += c0; eB1 += c1; rB0 += d0; rB1 += d1; }
            }
#pragma unroll
            for (int d = 1; d < 4; d <<= 1) {
                eA0 += __shfl_xor_sync(0xffffffffu, eA0, d);
                eB0 += __shfl_xor_sync(0xffffffffu, eB0, d);
                rA0 += __shfl_xor_sync(0xffffffffu, rA0, d);
                rB0 += __shfl_xor_sync(0xffffffffu, rB0, d);
                eA1 += __shfl_xor_sync(0xffffffffu, eA1, d);
                eB1 += __shfl_xor_sync(0xffffffffu, eB1, d);
                rA1 += __shfl_xor_sync(0xffffffffu, rA1, d);
                rB1 += __shfl_xor_sync(0xffffffffu, rB1, d);
            }
            if ((lane & 3) == 0) {
                int h0 = wn >> 5;
                if (gm0 < M) {
                    el[(size_t)gm0 * 4 + h0]     = eA0;
                    el[(size_t)gm0 * 4 + h0 + 1] = eB0;
                    if (gm0 < n_er) {
                        er[(size_t)gm0 * 4 + h0]     = rA0;
                        er[(size_t)gm0 * 4 + h0 + 1] = rB0;
                    }
                }
                if (gm1 < M) {
                    el[(size_t)gm1 * 4 + h0]     = eA1;
                    el[(size_t)gm1 * 4 + h0 + 1] = eB1;
                    if (gm1 < n_er) {
                        er[(size_t)gm1 * 4 + h0]     = rA1;
                        er[(size_t)gm1 * 4 + h0 + 1] = rB1;
                    }
                }
            }
        }
    }
}

// ---------------- CSR build ----------------
__global__ void fill_int_kernel(int* p, int n, int v) {
    int i = blockIdx.x * blockDim.x + threadIdx.x;
    if (i < n) p[i] = v;
}
__global__ void hist_kernel(const int* __restrict__ dstAll, int E, int* __restrict__ cnt) {
    int j = blockIdx.y;
    int e = blockIdx.x * blockDim.x + threadIdx.x;
    if (e < E) atomicAdd(&cnt[j * N_DST0 + dstAll[(size_t)j * E + e]], 1);
}
__global__ void scan_kernel(const int* __restrict__ cntAll, int* __restrict__ offsAll,
                            int* __restrict__ curAll, int n) {
    const int* cnt = cntAll + blockIdx.x * N_DST0;
    int* offs = offsAll + blockIdx.x * (N_DST0 + 1);
    int* cur  = curAll + blockIdx.x * N_DST0;
    __shared__ int wsum[32];
    __shared__ int running_s;
    if (threadIdx.x == 0) running_s = 0;
    __syncthreads();
    int lane = threadIdx.x & 31, wid = threadIdx.x >> 5;
    for (int base = 0; base < n; base += 1024) {
        int i = base + (int)threadIdx.x;
        int v = (i < n) ? cnt[i] : 0;
        int x = v;
#pragma unroll
        for (int d = 1; d < 32; d <<= 1) {
            int t = __shfl_up_sync(0xffffffffu, x, d);
            if (lane >= d) x += t;
        }
        if (lane == 31) wsum[wid] = x;
        __syncthreads();
        if (wid == 0) {
            int y = wsum[lane];
#pragma unroll
            for (int d = 1; d < 32; d <<= 1) {
                int t = __shfl_up_sync(0xffffffffu, y, d);
                if (lane >= d) y += t;
            }
            wsum[lane] = y;
        }
        __syncthreads();
        int incl = x + (wid ? wsum[wid - 1] : 0);
        int r = running_s;
        if (i < n) { int o = r + (incl - v); offs[i] = o; cur[i] = o; }
        int total = wsum[31];
        __syncthreads();
        if (threadIdx.x == 0) running_s = r + total;
        __syncthreads();
    }
    if (threadIdx.x == 0) offs[n] = running_s;
}
__global__ void scatter_kernel(const int* __restrict__ srcAll,
                               const int* __restrict__ dstAll, int E,
                               int* __restrict__ cur, int* __restrict__ eperm)
{
    int j = blockIdx.y;
    int e = blockIdx.x * blockDim.x + threadIdx.x;
    if (e >= E) return;
    int s = srcAll[(size_t)j * E + e];
    int d = dstAll[(size_t)j * E + e];
    int pos = atomicAdd(&cur[j * N_DST0 + d], 1);
    eperm[(size_t)j * E0 + pos] = s;
}

// ---------------- aggregation: one block (64 thr) per (dst, relation) ----------
__global__ void aggregate_rel_kernel(
    const __half* __restrict__ Hs, int hsrows,
    const float* __restrict__ el, const float* __restrict__ er,
    const int* __restrict__ offs, const int* __restrict__ eperm,
    int n_dst, float* __restrict__ out)
{
    int nd = blockIdx.x;
    int j = blockIdx.y;
    int t = threadIdx.x;
    int h = t >> 4;

    const __half* Hj = Hs + (size_t)j * hsrows * HID;
    const float* elj = el + (size_t)j * hsrows * 4;
    const float* erj = er + (size_t)j * n_dst * 4;
    const int* offj = offs + j * (N_DST0 + 1);
    const int* epj  = eperm + (size_t)j * E0;

    int o0 = offj[nd], o1 = offj[nd + 1];
    int cnt = o1 - o0;
    if (cnt == 0) return;

    __shared__ int   s_src[64];
    __shared__ float s_w[4][64];

    float er_all[4];
    {
        float4 e4 = *(const float4*)(erj + (size_t)nd * 4);
        er_all[0] = e4.x; er_all[1] = e4.y; er_all[2] = e4.z; er_all[3] = e4.w;
    }
    float2 acc = make_float2(0.f, 0.f);
    float ssum = 0.f;
    for (int c0 = 0; c0 < cnt; c0 += 64) {
        int k = c0 + t;
        if (k < cnt) {
            int s = epj[o0 + k];
            s_src[t] = s;
            float4 L = *(const float4*)(elj + (size_t)s * 4);
            float lv[4] = {L.x, L.y, L.z, L.w};
#pragma unroll
            for (int hh = 0; hh < 4; hh++) {
                float v = lv[hh] + er_all[hh];
                v = v > 0.f ? v : NEG_SLOPE * v;
                s_w[hh][t] = __expf(v);
            }
        }
        __syncthreads();
        int len = min(64, cnt - c0);
        const float* wrow = s_w[h];
#pragma unroll 4
        for (int k2 = 0; k2 < len; k2++) {
            float w = wrow[k2];
            __half2 x2 = *(const __half2*)(Hj + (size_t)s_src[k2] * HID + 2 * t);
            float2 xf = __half22float2(x2);
            acc.x += w * xf.x;
            acc.y += w * xf.y;
            ssum += w;
        }
        __syncthreads();
    }
    float inv = 1.f / ssum;
    float* op = out + (size_t)nd * HID + 2 * t;
    atomicAdd(op,     acc.x * inv);
    atomicAdd(op + 1, acc.y * inv);
}

// ---------------- column norm + activation ----------------
__global__ void colstat_zero_kernel() {
    int t = threadIdx.x;
    g_colsum[t] = 0.0; g_colsq[t] = 0.0;
}
__global__ void colstat_partial_kernel(const float* __restrict__ X, int nrows) {
    int t = threadIdx.x;
    int r0 = blockIdx.x * 256;
    int r1 = min(r0 + 256, nrows);
    float fs = 0.f, fq = 0.f;
    for (int r = r0; r < r1; r++) {
        float v = X[(size_t)r * HID + t];
        fs += v; fq += v * v;
    }
    atomicAdd(&g_colsum[t], (double)fs);
    atomicAdd(&g_colsq[t], (double)fq);
}
__global__ void colstat_final_kernel(int nrows) {
    int t = threadIdx.x;
    double inv = 1.0 / (double)nrows;
    double mean = g_colsum[t] * inv;
    double var = g_colsq[t] * inv - mean * mean;
    g_mean[t] = (float)mean;
    g_rstd[t] = (float)(1.0 / sqrt(var + (double)EPS_LN));
}
__global__ void norm_act_split_kernel(const float* __restrict__ X,
                                      const float* __restrict__ g,
                                      const float* __restrict__ be,
                                      fp16* __restrict__ hi, fp16* __restrict__ lo,
                                      int nrows, int act)
{
    int idx = blockIdx.x * blockDim.x + threadIdx.x;
    if (idx >= nrows * HID) return;
    int t = idx & (HID - 1);
    float v = (X[idx] - g_mean[t]) * g_rstd[t] * g[t] + be[t];
    if (act) v = v > 0.f ? v : 0.f;
    else     v = v > 0.f ? v : expm1f(v);
    fp16 h = __float2half(v);
    hi[idx] = h;
    lo[idx] = __float2half(v - __half2float(h));
}

// ---------------- host orchestration ----------------
static inline void* sym(const void* s) { void* p = nullptr; cudaGetSymbolAddress(&p, s); return p; }

static void set_smem_attrs() {
    cudaFuncSetAttribute(mma_gemm4<true,  false, true >, cudaFuncAttributeMaxDynamicSharedMemorySize, SMEM_BYTES);
    cudaFuncSetAttribute(mma_gemm4<false, true,  false>, cudaFuncAttributeMaxDynamicSharedMemorySize, SMEM_BYTES);
}

static void run_layer(const fp16* Ahi, const fp16* Alo, int n_src, int n_dst, int Kdim,
                      const fp16* Wt, const fp16* Ws,
                      const float* alpha_l, const float* alpha_r,
                      const float* bs,
                      const float* gamma, const float* beta,
                      const int* srcAll, const int* dstAll, int E,
                      __half* Hs, float* elbuf, float* erbuf,
                      float* accbuf, fp16* outhi, fp16* outlo)
{
    int* cnt = (int*)sym(g_cnt);
    int* offs = (int*)sym(g_offs);
    int* cur = (int*)sym(g_cur);
    int* eperm = (int*)sym(g_eperm);

    fill_int_kernel<<<(T_REL * N_DST0 + 255) / 256, 256>>>(cnt, T_REL * N_DST0, 0);

    {   // Hs = A @ W[j]^T for all relations (grid.x = relation for A-tile L2 reuse)
        dim3 grid(T_REL, (n_src + 127) / 128);
        mma_gemm4<true, false, true><<<grid, 256, SMEM_BYTES>>>(
            Ahi, Alo, Wt, nullptr, Hs,
            alpha_l, alpha_r, elbuf, erbuf, n_src, HID, Kdim, n_dst);
    }

    { dim3 grid((E + 255) / 256, T_REL);
      hist_kernel<<<grid, 256>>>(dstAll, E, cnt); }
    scan_kernel<<<T_REL, 1024>>>(cnt, offs, cur, n_dst);
    { dim3 grid((E + 255) / 256, T_REL);
      scatter_kernel<<<grid, 256>>>(srcAll, dstAll, E, cur, eperm); }

    {   // acc = A[:n_dst] @ Ws + bs (fp32 out)
        dim3 grid((n_dst + 127) / 128, 1);
        mma_gemm4<false, true, false><<<grid, 256, SMEM_BYTES>>>(
            Ahi, Alo, Ws, bs, accbuf,
            nullptr, nullptr, nullptr, nullptr, n_dst, HID, Kdim, 0);
    }

    { dim3 grid(n_dst, T_REL);
      aggregate_rel_kernel<<<grid, 64>>>(Hs, n_src, elbuf, erbuf, offs, eperm,
                                         n_dst, accbuf); }

    colstat_zero_kernel<<<1, 128>>>();
    colstat_partial_kernel<<<(n_dst + 255) / 256, 128>>>(accbuf, n_dst);
    colstat_final_kernel<<<1, 128>>>(n_dst);
    norm_act_split_kernel<<<(n_dst * HID + 255) / 256, 256>>>(accbuf, gamma, beta,
                                                              outhi, outlo, n_dst, 0);
}

extern "C" void kernel_launch(void* const* d_in, const int* in_sizes, int n_in,
                              void* d_out, int out_size)
{
    (void)in_sizes; (void)n_in; (void)out_size;
    const float* x   = (const float*)d_in[0];
    const float* W0  = (const float*)d_in[1];
    const float* al0 = (const float*)d_in[2];
    const float* ar0 = (const float*)d_in[3];
    const float* Ws0 = (const float*)d_in[5];
    const float* bs0 = (const float*)d_in[6];
    const float* g0  = (const float*)d_in[7];
    const float* be0 = (const float*)d_in[8];
    const float* W1  = (const float*)d_in[9];
    const float* al1 = (const float*)d_in[10];
    const float* ar1 = (const float*)d_in[11];
    const float* Ws1 = (const float*)d_in[13];
    const float* bs1 = (const float*)d_in[14];
    const float* g1  = (const float*)d_in[15];
    const float* be1 = (const float*)d_in[16];
    const float* Wm1 = (const float*)d_in[17];
    const float* bm1 = (const float*)d_in[18];
    const float* gm  = (const float*)d_in[19];
    const float* bem = (const float*)d_in[20];
    const float* Wm2 = (const float*)d_in[21];
    const float* bm2 = (const float*)d_in[22];
    const int* src0  = (const int*)d_in[23];
    const int* dst0  = (const int*)d_in[24];
    const int* src1  = (const int*)d_in[25];
    const int* dst1  = (const int*)d_in[26];
    float* out = (float*)d_out;

    __half* Hs0 = (__half*)sym(g_Hs0);
    __half* Hs1 = (__half*)sym(g_Hs1);
    float* el0p = (float*)sym(g_el0);
    float* er0p = (float*)sym(g_er0);
    float* el1p = (float*)sym(g_el1);
    float* er1p = (float*)sym(g_er1);
    float* acc0 = (float*)sym(g_acc0);
    float* acc1 = (float*)sym(g_acc1);
    float* mlp  = (float*)sym(g_mlp);
    fp16* xhi = (fp16*)sym(g_xhi);
    fp16* xlo = (fp16*)sym(g_xlo);
    fp16* shi = (fp16*)sym(g_shi);
    fp16* slo = (fp16*)sym(g_slo);
    fp16* thi = (fp16*)sym(g_thi);
    fp16* tlo = (fp16*)sym(g_tlo);
    fp16* wt  = (fp16*)sym(g_wt);

    set_smem_attrs();

    {
        dim3 g((T_REL * HID * IN_DIM + 255) / 256, 6);
        splitw_all_kernel<<<g, 256>>>(W0, Ws0, W1, Ws1, Wm1, Wm2, wt);
    }
    {
        size_t n = (size_t)N_SRC0 * IN_DIM;
        split_kernel<<<(unsigned)((n + 255) / 256), 256>>>(x, xhi, xlo, n);
    }

    // Layer 0
    run_layer(xhi, xlo, N_SRC0, N_DST0, IN_DIM,
              wt + W0T_OFF, wt + WS0T_OFF,
              al0, ar0, bs0, g0, be0,
              src0, dst0, E0, Hs0, el0p, er0p, acc0, shi, slo);

    // Layer 1
    run_layer(shi, slo, N_DST0, N_DST1, HID,
              wt + W1T_OFF, wt + WS1T_OFF,
              al1, ar1, bs1, g1, be1,
              src1, dst1, E1, Hs1, el1p, er1p, acc1, thi, tlo);

    // MLP
    {
        dim3 grid((N_DST1 + 127) / 128, 1);
        mma_gemm4<false, true, false><<<grid, 256, SMEM_BYTES>>>(
            thi, tlo, wt + WM1T_OFF, bm1, mlp,
            nullptr, nullptr, nullptr, nullptr, N_DST1, HID, HID, 0);
    }
    colstat_zero_kernel<<<1, 128>>>();
    colstat_partial_kernel<<<(N_DST1 + 255) / 256, 128>>>(mlp, N_DST1);
    colstat_final_kernel<<<1, 128>>>(N_DST1);
    norm_act_split_kernel<<<(N_DST1 * HID + 255) / 256, 256>>>(mlp, gm, bem, shi, slo, N_DST1, 1);
    {
        dim3 grid((N_DST1 + 127) / 128, (OUT_DIM + 127) / 128);
        mma_gemm4<false, true, false><<<grid, 256, SMEM_BYTES>>>(
            shi, slo, wt + WM2T_OFF, bm2, out,
            nullptr, nullptr, nullptr, nullptr, N_DST1, OUT_DIM, HID, 0);
    }
}

// round 17
// speedup vs baseline: 1.1721x; 1.0072x over previous
#include <cuda_runtime.h>
#include <cuda_fp16.h>
#include <cstdint>

#define N_SRC0 120000
#define N_DST0 40000
#define N_DST1 10000
#define T_REL  5
#define HID    128
#define IN_DIM 256
#define OUT_DIM 153
#define E0 800000
#define E1 300000
#define NEG_SLOPE 0.2f
#define EPS_LN 1e-5f

typedef __half fp16;

// ---------------- static device scratch ----------------
__device__ __align__(128) __half g_Hs0[(size_t)T_REL * N_SRC0 * HID];
__device__ __align__(128) __half g_Hs1[(size_t)T_REL * N_DST0 * HID];
__device__ __align__(16)  float g_el0[(size_t)T_REL * N_SRC0 * 4];
__device__ __align__(16)  float g_er0[(size_t)T_REL * N_DST0 * 4];
__device__ __align__(16)  float g_el1[(size_t)T_REL * N_DST0 * 4];
__device__ __align__(16)  float g_er1[(size_t)T_REL * N_DST1 * 4];
__device__ __align__(128) float g_acc0[(size_t)N_DST0 * HID];
__device__ __align__(128) float g_acc1[(size_t)N_DST1 * HID];
__device__ __align__(128) float g_mlp[(size_t)N_DST1 * HID];
__device__ int      g_cnt[T_REL * N_DST0];
__device__ int      g_offs[T_REL * (N_DST0 + 1)];
__device__ int      g_cur[T_REL * N_DST0];
__device__ int      g_eperm[T_REL * E0];      // stores SRC node id
__device__ double   g_colsum[HID];
__device__ double   g_colsq[HID];
__device__ float    g_mean[HID];
__device__ float    g_rstd[HID];
__device__ __align__(128) fp16 g_xhi[(size_t)N_SRC0 * IN_DIM];
__device__ __align__(128) fp16 g_xlo[(size_t)N_SRC0 * IN_DIM];
__device__ __align__(128) fp16 g_shi[(size_t)N_DST0 * HID];
__device__ __align__(128) fp16 g_slo[(size_t)N_DST0 * HID];
__device__ __align__(128) fp16 g_thi[(size_t)N_DST1 * HID];
__device__ __align__(128) fp16 g_tlo[(size_t)N_DST1 * HID];
#define W0T_OFF   0
#define WS0T_OFF  163840
#define W1T_OFF   196608
#define WS1T_OFF  278528
#define WM1T_OFF  294912
#define WM2T_OFF  311296
#define WT_TOTAL  330880
__device__ __align__(128) fp16 g_wt[WT_TOTAL];   // single fp16 weights [N][K]

// ---------------- helpers ----------------
__device__ __forceinline__ void cp_async16(uint32_t dst, const void* src, int sz) {
    asm volatile("cp.async.cg.shared.global [%0], [%1], 16, %2;\n"
                 :: "r"(dst), "l"(src), "r"(sz));
}
__device__ __forceinline__ void cp_commit() {
    asm volatile("cp.async.commit_group;\n");
}
__device__ __forceinline__ void ldsm4(uint32_t* r, uint32_t addr) {
    asm volatile("ldmatrix.sync.aligned.m8n8.x4.shared.b16 {%0,%1,%2,%3}, [%4];"
        : "=r"(r[0]), "=r"(r[1]), "=r"(r[2]), "=r"(r[3]) : "r"(addr));
}
__device__ __forceinline__ void mma16816(float* c, const uint32_t* a, uint32_t b0, uint32_t b1) {
    asm volatile("mma.sync.aligned.m16n8k16.row.col.f32.f16.f16.f32 "
        "{%0,%1,%2,%3}, {%4,%5,%6,%7}, {%8,%9}, {%0,%1,%2,%3};"
        : "+f"(c[0]), "+f"(c[1]), "+f"(c[2]), "+f"(c[3])
        : "r"(a[0]), "r"(a[1]), "r"(a[2]), "r"(a[3]), "r"(b0), "r"(b1));
}

// ---------------- split kernels ----------------
__global__ void split_kernel(const float* __restrict__ X, fp16* __restrict__ hi,
                             fp16* __restrict__ lo, size_t n)
{
    size_t i = (size_t)blockIdx.x * blockDim.x + threadIdx.x;
    if (i >= n) return;
    float v = X[i];
    fp16 h = __float2half(v);
    hi[i] = h;
    lo[i] = __float2half(v - __half2float(h));
}
__global__ void splitw_all_kernel(
    const float* __restrict__ W0, const float* __restrict__ Ws0,
    const float* __restrict__ W1, const float* __restrict__ Ws1,
    const float* __restrict__ Wm1, const float* __restrict__ Wm2,
    fp16* __restrict__ wT)
{
    int seg = blockIdx.y;
    const float* W; int K, N, nrel, off;
    switch (seg) {
        case 0:  W = W0;  K = IN_DIM; N = HID;     nrel = T_REL; off = W0T_OFF;  break;
        case 1:  W = Ws0; K = IN_DIM; N = HID;     nrel = 1;     off = WS0T_OFF; break;
        case 2:  W = W1;  K = HID;    N = HID;     nrel = T_REL; off = W1T_OFF;  break;
        case 3:  W = Ws1; K = HID;    N = HID;     nrel = 1;     off = WS1T_OFF; break;
        case 4:  W = Wm1; K = HID;    N = HID;     nrel = 1;     off = WM1T_OFF; break;
        default: W = Wm2; K = HID;    N = OUT_DIM; nrel = 1;     off = WM2T_OFF; break;
    }
    int total = nrel * N * K;
    int idx = blockIdx.x * blockDim.x + threadIdx.x;
    if (idx >= total) return;
    int j = idx / (N * K);
    int rem = idx - j * (N * K);
    int n = rem / K, k = rem - n * K;
    wT[off + idx] = __float2half(W[((size_t)j * K + k) * N + n]);
}

// ---------------- fused fp16x2 MMA GEMM, 3-stage, 256 thr, 2 CTA/SM ----------
#define GSTRIDE  40
#define SM_TILE  (128 * GSTRIDE)
#define SM_AHI   0
#define SM_ALO   SM_TILE
#define SM_B     (2 * SM_TILE)
#define SM_STAGE (3 * SM_TILE)               // 15360 elements = 30720 B
#define SMEM_BYTES (3 * SM_STAGE * 2)        // 92160 B

template<bool REL, bool HASBIAS, bool EPI>
__global__ void __launch_bounds__(256, 2) mma_gemm4(
    const fp16* __restrict__ Ahi, const fp16* __restrict__ Alo,
    const fp16* __restrict__ BT,
    const float* __restrict__ bias, void* __restrict__ Cv,
    const float* __restrict__ al, const float* __restrict__ ar,
    float* __restrict__ el, float* __restrict__ er,
    int M, int N, int K, int n_er)
{
    extern __shared__ fp16 sm[];

    __half* Ch = (__half*)Cv;
    float*  Cf = (float*)Cv;

    int bm0, bn0, ldc;
    if (REL) {
        int j = blockIdx.x;
        bm0 = blockIdx.y * 128;
        BT += (size_t)j * 128 * K;
        Ch += (size_t)j * M * 128;
        if (EPI) {
            al += (size_t)j * HID;  ar += (size_t)j * HID;
            el += (size_t)j * M * 4; er += (size_t)j * n_er * 4;
        }
        bn0 = 0; ldc = 128; N = 128;
    } else {
        bm0 = blockIdx.x * 128;
        bn0 = blockIdx.y * 128; ldc = N;
    }

    int tid = threadIdx.x, lane = tid & 31, warp = tid >> 5;
    int wm = (warp & 3) * 32, wn = (warp >> 2) * 64;

    int kc = K >> 5;

    int ldrow = tid >> 2;
    int ldcol = (tid & 3) << 3;

    uint32_t s0 = (uint32_t)__cvta_generic_to_shared(sm);

    int mrowA = lane & 15, mcolA = (lane >> 4) << 3;
    int mrowB = (lane & 7) | ((lane >> 4) << 3);
    int mcolB = ((lane >> 3) & 1) << 3;

    float acc[2][8][4];
#pragma unroll
    for (int a = 0; a < 2; a++)
#pragma unroll
        for (int b = 0; b < 8; b++)
#pragma unroll
            for (int c = 0; c < 4; c++) acc[a][b][c] = 0.f;

#define LOAD_STAGE(IT, ST) do {                                                  \
    int kk_ = (IT) << 5;                                                         \
    uint32_t sb_ = s0 + (uint32_t)(ST) * (SM_STAGE * 2);                         \
    _Pragma("unroll")                                                            \
    for (int hh = 0; hh < 2; hh++) {                                             \
        int row = ldrow + hh * 64;                                               \
        int gm = bm0 + row;                                                      \
        int ok = gm < M;                                                         \
        size_t aoff = (size_t)(ok ? gm : 0) * K + kk_ + ldcol;                   \
        cp_async16(sb_ + (SM_AHI + row * GSTRIDE + ldcol) * 2, Ahi + aoff, ok ? 16 : 0); \
        cp_async16(sb_ + (SM_ALO + row * GSTRIDE + ldcol) * 2, Alo + aoff, ok ? 16 : 0); \
        int gn = bn0 + row;                                                      \
        int okb = gn < N;                                                        \
        size_t boff = (size_t)(okb ? gn : 0) * K + kk_ + ldcol;                  \
        cp_async16(sb_ + (SM_B + row * GSTRIDE + ldcol) * 2, BT + boff, okb ? 16 : 0); \
    }                                                                            \
    cp_commit();                                                                 \
} while (0)

    LOAD_STAGE(0, 0);
    LOAD_STAGE(1, 1);

    for (int it = 0; it < kc; it++) {
        int st = it % 3;
        if (it + 1 < kc) {
            asm volatile("cp.async.wait_group 1;\n" ::: "memory");
        } else {
            asm volatile("cp.async.wait_group 0;\n" ::: "memory");
        }
        __syncthreads();

        uint32_t base = s0 + (uint32_t)st * (SM_STAGE * 2);
#pragma unroll
        for (int s = 0; s < 2; s++) {
            uint32_t ahi[2][4], alo2[2][4];
#pragma unroll
            for (int mt = 0; mt < 2; mt++) {
                uint32_t ra = (wm + mt * 16 + mrowA) * GSTRIDE + s * 16 + mcolA;
                ldsm4(ahi[mt],  base + (SM_AHI + ra) * 2);
                ldsm4(alo2[mt], base + (SM_ALO + ra) * 2);
            }
#pragma unroll
            for (int np = 0; np < 4; np++) {
                uint32_t b[4];
                ldsm4(b, base + (SM_B + (wn + np * 16 + mrowB) * GSTRIDE + s * 16 + mcolB) * 2);
#pragma unroll
                for (int mt = 0; mt < 2; mt++) {
                    mma16816(acc[mt][2 * np],     ahi[mt],  b[0], b[1]);
                    mma16816(acc[mt][2 * np + 1], ahi[mt],  b[2], b[3]);
                    mma16816(acc[mt][2 * np],     alo2[mt], b[0], b[1]);
                    mma16816(acc[mt][2 * np + 1], alo2[mt], b[2], b[3]);
                }
            }
        }
        if (it + 2 < kc) LOAD_STAGE(it + 2, (it + 2) % 3);
    }
#undef LOAD_STAGE

    int trow = lane >> 2, tcol = (lane & 3) << 1;
#pragma unroll
    for (int mt = 0; mt < 2; mt++) {
        int gm0 = bm0 + wm + mt * 16 + trow;
        int gm1 = gm0 + 8;
#pragma unroll
        for (int nt = 0; nt < 8; nt++) {
            int gn = bn0 + wn + nt * 8 + tcol;
            float* cr = acc[mt][nt];
            if (REL) {
                if (gm0 < M) {
                    Ch[(size_t)gm0 * ldc + gn]     = __float2half(cr[0]);
                    Ch[(size_t)gm0 * ldc + gn + 1] = __float2half(cr[1]);
                }
                if (gm1 < M) {
                    Ch[(size_t)gm1 * ldc + gn]     = __float2half(cr[2]);
                    Ch[(size_t)gm1 * ldc + gn + 1] = __float2half(cr[3]);
                }
            } else {
                bool okn0 = gn < N, okn1 = gn + 1 < N;
                float b0a = 0.f, b1a = 0.f;
                if (HASBIAS) {
                    if (okn0) b0a = bias[gn];
                    if (okn1) b1a = bias[gn + 1];
                }
                if (gm0 < M) {
                    if (okn0) Cf[(size_t)gm0 * ldc + gn]     = cr[0] + b0a;
                    if (okn1) Cf[(size_t)gm0 * ldc + gn + 1] = cr[1] + b1a;
                }
                if (gm1 < M) {
                    if (okn0) Cf[(size_t)gm1 * ldc + gn]     = cr[2] + b0a;
                    if (okn1) Cf[(size_t)gm1 * ldc + gn + 1] = cr[3] + b1a;
                }
            }
        }
        if (EPI) {
            float eA0 = 0.f, eB0 = 0.f, rA0 = 0.f, rB0 = 0.f;
            float eA1 = 0.f, eB1 = 0.f, rA1 = 0.f, rB1 = 0.f;
#pragma unroll
            for (int nt = 0; nt < 8; nt++) {
                int gn = wn + nt * 8 + tcol;
                float a0v = al[gn], a1v = al[gn + 1];
                float r0v = ar[gn], r1v = ar[gn + 1];
                float* cr = acc[mt][nt];
                float c0 = cr[0] * a0v + cr[1] * a1v;
                float c1 = cr[2] * a0v + cr[3] * a1v;
                float d0 = cr[0] * r0v + cr[1] * r1v;
                float d1 = cr[2] * r0v + cr[3] * r1v;
                if (nt < 4) { eA0 += c0; eA1 += c1; rA0 += d0; rA1 += d1; }
                else        { eB0 += c0; eB1 += c1; rB0 += d0; rB1 += d1; }
            }
#pragma unroll
            for (int d = 1; d < 4; d <<= 1) {
                eA0 += __shfl_xor_sync(0xffffffffu, eA0, d);
                eB0 += __shfl_xor_sync(0xffffffffu, eB0, d);
                rA0 += __shfl_xor_sync(0xffffffffu, rA0, d);
                rB0 += __shfl_xor_sync(0xffffffffu, rB0, d);
                eA1 += __shfl_xor_sync(0xffffffffu, eA1, d);
                eB1 += __shfl_xor_sync(0xffffffffu, eB1, d);
                rA1 += __shfl_xor_sync(0xffffffffu, rA1, d);
                rB1 += __shfl_xor_sync(0xffffffffu, rB1, d);
            }
            if ((lane & 3) == 0) {
                int h0 = wn >> 5;
                if (gm0 < M) {
                    el[(size_t)gm0 * 4 + h0]     = eA0;
                    el[(size_t)gm0 * 4 + h0 + 1] = eB0;
                    if (gm0 < n_er) {
                        er[(size_t)gm0 * 4 + h0]     = rA0;
                        er[(size_t)gm0 * 4 + h0 + 1] = rB0;
                    }
                }
                if (gm1 < M) {
                    el[(size_t)gm1 * 4 + h0]     = eA1;
                    el[(size_t)gm1 * 4 + h0 + 1] = eB1;
                    if (gm1 < n_er) {
                        er[(size_t)gm1 * 4 + h0]     = rA1;
                        er[(size_t)gm1 * 4 + h0 + 1] = rB1;
                    }
                }
            }
        }
    }
}

// ---------------- CSR build ----------------
__global__ void fill_int_kernel(int* p, int n, int v) {
    int i = blockIdx.x * blockDim.x + threadIdx.x;
    if (i < n) p[i] = v;
}
__global__ void hist_kernel(const int* __restrict__ dstAll, int E, int* __restrict__ cnt) {
    int j = blockIdx.y;
    int e = blockIdx.x * blockDim.x + threadIdx.x;
    if (e < E) atomicAdd(&cnt[j * N_DST0 + dstAll[(size_t)j * E + e]], 1);
}
__global__ void scan_kernel(const int* __restrict__ cntAll, int* __restrict__ offsAll,
                            int* __restrict__ curAll, int n) {
    const int* cnt = cntAll + blockIdx.x * N_DST0;
    int* offs = offsAll + blockIdx.x * (N_DST0 + 1);
    int* cur  = curAll + blockIdx.x * N_DST0;
    __shared__ int wsum[32];
    __shared__ int running_s;
    if (threadIdx.x == 0) running_s = 0;
    __syncthreads();
    int lane = threadIdx.x & 31, wid = threadIdx.x >> 5;
    for (int base = 0; base < n; base += 1024) {
        int i = base + (int)threadIdx.x;
        int v = (i < n) ? cnt[i] : 0;
        int x = v;
#pragma unroll
        for (int d = 1; d < 32; d <<= 1) {
            int t = __shfl_up_sync(0xffffffffu, x, d);
            if (lane >= d) x += t;
        }
        if (lane == 31) wsum[wid] = x;
        __syncthreads();
        if (wid == 0) {
            int y = wsum[lane];
#pragma unroll
            for (int d = 1; d < 32; d <<= 1) {
                int t = __shfl_up_sync(0xffffffffu, y, d);
                if (lane >= d) y += t;
            }
            wsum[lane] = y;
        }
        __syncthreads();
        int incl = x + (wid ? wsum[wid - 1] : 0);
        int r = running_s;
        if (i < n) { int o = r + (incl - v); offs[i] = o; cur[i] = o; }
        int total = wsum[31];
        __syncthreads();
        if (threadIdx.x == 0) running_s = r + total;
        __syncthreads();
    }
    if (threadIdx.x == 0) offs[n] = running_s;
}
__global__ void scatter_kernel(const int* __restrict__ srcAll,
                               const int* __restrict__ dstAll, int E,
                               int* __restrict__ cur, int* __restrict__ eperm)
{
    int j = blockIdx.y;
    int e = blockIdx.x * blockDim.x + threadIdx.x;
    if (e >= E) return;
    int s = srcAll[(size_t)j * E + e];
    int d = dstAll[(size_t)j * E + e];
    int pos = atomicAdd(&cur[j * N_DST0 + d], 1);
    eperm[(size_t)j * E0 + pos] = s;
}

// ---------------- aggregation: one WARP per (dst, relation), no smem/barriers --
// lane owns cols [4*lane, 4*lane+4); head = lane>>3. Broadcast loads for src/el.
__global__ void __launch_bounds__(256) aggregate_warp_kernel(
    const __half* __restrict__ Hs, int hsrows,
    const float* __restrict__ el, const float* __restrict__ er,
    const int* __restrict__ offs, const int* __restrict__ eperm,
    int n_dst, float* __restrict__ out)
{
    int gw = blockIdx.x * (blockDim.x >> 5) + (threadIdx.x >> 5);
    int total = n_dst * T_REL;
    if (gw >= total) return;
    int j  = gw / n_dst;            // relation-major: one relation's warps adjacent
    int nd = gw - j * n_dst;
    int lane = threadIdx.x & 31;
    int h = lane >> 3;

    const __half* Hj = Hs + (size_t)j * hsrows * HID;
    const float* elj = el + (size_t)j * hsrows * 4;
    const float* erj = er + (size_t)j * n_dst * 4;
    const int* offj = offs + j * (N_DST0 + 1);
    const int* epj  = eperm + (size_t)j * E0;

    int o0 = offj[nd], o1 = offj[nd + 1];
    if (o0 == o1) return;

    float4 e4 = *(const float4*)(erj + (size_t)nd * 4);
    float erh = (h == 0) ? e4.x : (h == 1) ? e4.y : (h == 2) ? e4.z : e4.w;

    float a0 = 0.f, a1 = 0.f, a2 = 0.f, a3 = 0.f, ssum = 0.f;
    for (int k = o0; k < o1; k++) {
        int s = epj[k];                                    // broadcast
        float4 L = *(const float4*)(elj + (size_t)s * 4);  // broadcast
        float lv = (h == 0) ? L.x : (h == 1) ? L.y : (h == 2) ? L.z : L.w;
        float v = lv + erh;
        v = v > 0.f ? v : NEG_SLOPE * v;
        float w = __expf(v);
        const __half2* hp = (const __half2*)(Hj + (size_t)s * HID + 4 * lane);
        float2 x0 = __half22float2(hp[0]);
        float2 x1 = __half22float2(hp[1]);
        a0 += w * x0.x; a1 += w * x0.y;
        a2 += w * x1.x; a3 += w * x1.y;
        ssum += w;
    }
    float inv = 1.f / ssum;
    float* op = out + (size_t)nd * HID + 4 * lane;
    atomicAdd(op,     a0 * inv);
    atomicAdd(op + 1, a1 * inv);
    atomicAdd(op + 2, a2 * inv);
    atomicAdd(op + 3, a3 * inv);
}

// ---------------- column norm + activation ----------------
__global__ void colstat_zero_kernel() {
    int t = threadIdx.x;
    g_colsum[t] = 0.0; g_colsq[t] = 0.0;
}
__global__ void colstat_partial_kernel(const float* __restrict__ X, int nrows) {
    int t = threadIdx.x;
    int r0 = blockIdx.x * 256;
    int r1 = min(r0 + 256, nrows);
    float fs = 0.f, fq = 0.f;
    for (int r = r0; r < r1; r++) {
        float v = X[(size_t)r * HID + t];
        fs += v; fq += v * v;
    }
    atomicAdd(&g_colsum[t], (double)fs);
    atomicAdd(&g_colsq[t], (double)fq);
}
__global__ void colstat_final_kernel(int nrows) {
    int t = threadIdx.x;
    double inv = 1.0 / (double)nrows;
    double mean = g_colsum[t] * inv;
    double var = g_colsq[t] * inv - mean * mean;
    g_mean[t] = (float)mean;
    g_rstd[t] = (float)(1.0 / sqrt(var + (double)EPS_LN));
}
__global__ void norm_act_split_kernel(const float* __restrict__ X,
                                      const float* __restrict__ g,
                                      const float* __restrict__ be,
                                      fp16* __restrict__ hi, fp16* __restrict__ lo,
                                      int nrows, int act)
{
    int idx = blockIdx.x * blockDim.x + threadIdx.x;
    if (idx >= nrows * HID) return;
    int t = idx & (HID - 1);
    float v = (X[idx] - g_mean[t]) * g_rstd[t] * g[t] + be[t];
    if (act) v = v > 0.f ? v : 0.f;
    else     v = v > 0.f ? v : expm1f(v);
    fp16 h = __float2half(v);
    hi[idx] = h;
    lo[idx] = __float2half(v - __half2float(h));
}

// ---------------- host orchestration ----------------
static inline void* sym(const void* s) { void* p = nullptr; cudaGetSymbolAddress(&p, s); return p; }

static void set_smem_attrs() {
    cudaFuncSetAttribute(mma_gemm4<true,  false, true >, cudaFuncAttributeMaxDynamicSharedMemorySize, SMEM_BYTES);
    cudaFuncSetAttribute(mma_gemm4<false, true,  false>, cudaFuncAttributeMaxDynamicSharedMemorySize, SMEM_BYTES);
}

static void run_layer(const fp16* Ahi, const fp16* Alo, int n_src, int n_dst, int Kdim,
                      const fp16* Wt, const fp16* Ws,
                      const float* alpha_l, const float* alpha_r,
                      const float* bs,
                      const float* gamma, const float* beta,
                      const int* srcAll, const int* dstAll, int E,
                      __half* Hs, float* elbuf, float* erbuf,
                      float* accbuf, fp16* outhi, fp16* outlo)
{
    int* cnt = (int*)sym(g_cnt);
    int* offs = (int*)sym(g_offs);
    int* cur = (int*)sym(g_cur);
    int* eperm = (int*)sym(g_eperm);

    fill_int_kernel<<<(T_REL * N_DST0 + 255) / 256, 256>>>(cnt, T_REL * N_DST0, 0);

    {   // Hs = A @ W[j]^T for all relations (grid.x = relation for A-tile L2 reuse)
        dim3 grid(T_REL, (n_src + 127) / 128);
        mma_gemm4<true, false, true><<<grid, 256, SMEM_BYTES>>>(
            Ahi, Alo, Wt, nullptr, Hs,
            alpha_l, alpha_r, elbuf, erbuf, n_src, HID, Kdim, n_dst);
    }

    { dim3 grid((E + 255) / 256, T_REL);
      hist_kernel<<<grid, 256>>>(dstAll, E, cnt); }
    scan_kernel<<<T_REL, 1024>>>(cnt, offs, cur, n_dst);
    { dim3 grid((E + 255) / 256, T_REL);
      scatter_kernel<<<grid, 256>>>(srcAll, dstAll, E, cur, eperm); }

    {   // acc = A[:n_dst] @ Ws + bs (fp32 out)
        dim3 grid((n_dst + 127) / 128, 1);
        mma_gemm4<false, true, false><<<grid, 256, SMEM_BYTES>>>(
            Ahi, Alo, Ws, bs, accbuf,
            nullptr, nullptr, nullptr, nullptr, n_dst, HID, Kdim, 0);
    }

    {   int totalw = n_dst * T_REL;
        aggregate_warp_kernel<<<(totalw * 32 + 255) / 256, 256>>>(
            Hs, n_src, elbuf, erbuf, offs, eperm, n_dst, accbuf); }

    colstat_zero_kernel<<<1, 128>>>();
    colstat_partial_kernel<<<(n_dst + 255) / 256, 128>>>(accbuf, n_dst);
    colstat_final_kernel<<<1, 128>>>(n_dst);
    norm_act_split_kernel<<<(n_dst * HID + 255) / 256, 256>>>(accbuf, gamma, beta,
                                                              outhi, outlo, n_dst, 0);
}

extern "C" void kernel_launch(void* const* d_in, const int* in_sizes, int n_in,
                              void* d_out, int out_size)
{
    (void)in_sizes; (void)n_in; (void)out_size;
    const float* x   = (const float*)d_in[0];
    const float* W0  = (const float*)d_in[1];
    const float* al0 = (const float*)d_in[2];
    const float* ar0 = (const float*)d_in[3];
    const float* Ws0 = (const float*)d_in[5];
    const float* bs0 = (const float*)d_in[6];
    const float* g0  = (const float*)d_in[7];
    const float* be0 = (const float*)d_in[8];
    const float* W1  = (const float*)d_in[9];
    const float* al1 = (const float*)d_in[10];
    const float* ar1 = (const float*)d_in[11];
    const float* Ws1 = (const float*)d_in[13];
    const float* bs1 = (const float*)d_in[14];
    const float* g1  = (const float*)d_in[15];
    const float* be1 = (const float*)d_in[16];
    const float* Wm1 = (const float*)d_in[17];
    const float* bm1 = (const float*)d_in[18];
    const float* gm  = (const float*)d_in[19];
    const float* bem = (const float*)d_in[20];
    const float* Wm2 = (const float*)d_in[21];
    const float* bm2 = (const float*)d_in[22];
    const int* src0  = (const int*)d_in[23];
    const int* dst0  = (const int*)d_in[24];
    const int* src1  = (const int*)d_in[25];
    const int* dst1  = (const int*)d_in[26];
    float* out = (float*)d_out;

    __half* Hs0 = (__half*)sym(g_Hs0);
    __half* Hs1 = (__half*)sym(g_Hs1);
    float* el0p = (float*)sym(g_el0);
    float* er0p = (float*)sym(g_er0);
    float* el1p = (float*)sym(g_el1);
    float* er1p = (float*)sym(g_er1);
    float* acc0 = (float*)sym(g_acc0);
    float* acc1 = (float*)sym(g_acc1);
    float* mlp  = (float*)sym(g_mlp);
    fp16* xhi = (fp16*)sym(g_xhi);
    fp16* xlo = (fp16*)sym(g_xlo);
    fp16* shi = (fp16*)sym(g_shi);
    fp16* slo = (fp16*)sym(g_slo);
    fp16* thi = (fp16*)sym(g_thi);
    fp16* tlo = (fp16*)sym(g_tlo);
    fp16* wt  = (fp16*)sym(g_wt);

    set_smem_attrs();

    {
        dim3 g((T_REL * HID * IN_DIM + 255) / 256, 6);
        splitw_all_kernel<<<g, 256>>>(W0, Ws0, W1, Ws1, Wm1, Wm2, wt);
    }
    {
        size_t n = (size_t)N_SRC0 * IN_DIM;
        split_kernel<<<(unsigned)((n + 255) / 256), 256>>>(x, xhi, xlo, n);
    }

    // Layer 0
    run_layer(xhi, xlo, N_SRC0, N_DST0, IN_DIM,
              wt + W0T_OFF, wt + WS0T_OFF,
              al0, ar0, bs0, g0, be0,
              src0, dst0, E0, Hs0, el0p, er0p, acc0, shi, slo);

    // Layer 1
    run_layer(shi, slo, N_DST0, N_DST1, HID,
              wt + W1T_OFF, wt + WS1T_OFF,
              al1, ar1, bs1, g1, be1,
              src1, dst1, E1, Hs1, el1p, er1p, acc1, thi, tlo);

    // MLP
    {
        dim3 grid((N_DST1 + 127) / 128, 1);
        mma_gemm4<false, true, false><<<grid, 256, SMEM_BYTES>>>(
            thi, tlo, wt + WM1T_OFF, bm1, mlp,
            nullptr, nullptr, nullptr, nullptr, N_DST1, HID, HID, 0);
    }
    colstat_zero_kernel<<<1, 128>>>();
    colstat_partial_kernel<<<(N_DST1 + 255) / 256, 128>>>(mlp, N_DST1);
    colstat_final_kernel<<<1, 128>>>(N_DST1);
    norm_act_split_kernel<<<(N_DST1 * HID + 255) / 256, 256>>>(mlp, gm, bem, shi, slo, N_DST1, 1);
    {
        dim3 grid((N_DST1 + 127) / 128, (OUT_DIM + 127) / 128);
        mma_gemm4<false, true, false><<<grid, 256, SMEM_BYTES>>>(
            shi, slo, wt + WM2T_OFF, bm2, out,
            nullptr, nullptr, nullptr, nullptr, N_DST1, OUT_DIM, HID, 0);
    }
}